// round 1
// baseline (speedup 1.0000x reference)
#include <cuda_runtime.h>

#define T_SEQ 2048
#define HID   4096
#define QKV_N 6144
#define HD    128
#define NHEADS 32
#define ATTN_SCALE 0.08838834764831845f   // 128^-0.5
#define ATTN_SMEM (5 * 64 * 132 * 4)      // Qh,Ql,Kh,Kl,V tiles (P overlays Kh)

// Scratch (allocation-free rule: __device__ globals)
__device__ float g_qkv[(size_t)T_SEQ * QKV_N];   // QKV projection output
__device__ float g_attn[(size_t)T_SEQ * HID];    // attention output (pre-Wo)

// ---------------------------------------------------------------------------
// helpers
// ---------------------------------------------------------------------------
__device__ __forceinline__ unsigned f2tf(float f) {
  unsigned u;
  asm("cvt.rna.tf32.f32 %0, %1;" : "=r"(u) : "f"(f));
  return u;
}

__device__ __forceinline__ void mma_tf32(float d[4], const unsigned a[4],
                                         unsigned b0, unsigned b1) {
  asm volatile(
      "mma.sync.aligned.m16n8k8.row.col.f32.tf32.tf32.f32 "
      "{%0,%1,%2,%3}, {%4,%5,%6,%7}, {%8,%9}, {%0,%1,%2,%3};"
      : "+f"(d[0]), "+f"(d[1]), "+f"(d[2]), "+f"(d[3])
      : "r"(a[0]), "r"(a[1]), "r"(a[2]), "r"(a[3]), "r"(b0), "r"(b1));
}

// ---------------------------------------------------------------------------
// 3xTF32 GEMM: C[M,N] = A[M,K] @ B[K,N], all row-major fp32.
// BM=128, BN=128, BK=16. 256 threads = 8 warps (4x2), warp tile 32x64.
// M,N,K assumed multiples of the tile sizes (true for all our shapes).
// ---------------------------------------------------------------------------
__global__ void gemm3_tf32(const float* __restrict__ A, const float* __restrict__ B,
                           float* __restrict__ C, int M, int N, int K) {
  __shared__ unsigned Ah[128][20];
  __shared__ unsigned Al[128][20];
  __shared__ unsigned Bh[16][132];
  __shared__ unsigned Bl[16][132];

  const int tid  = threadIdx.x;
  const int lane = tid & 31;
  const int warp = tid >> 5;
  const int g  = lane >> 2;      // group id (0..7)
  const int tg = lane & 3;       // thread-in-group (0..3)
  const int wm = warp & 3;       // warp row 0..3
  const int wn = warp >> 2;      // warp col 0..1
  const int bm = blockIdx.y * 128;
  const int bn = blockIdx.x * 128;

  float acc[2][8][4];
#pragma unroll
  for (int i = 0; i < 2; i++)
#pragma unroll
    for (int j = 0; j < 8; j++)
#pragma unroll
      for (int r = 0; r < 4; r++) acc[i][j][r] = 0.f;

  const int arow = tid >> 1;        // 0..127
  const int acol = (tid & 1) * 8;   // 0 or 8
  const int brow = tid >> 4;        // 0..15
  const int bcol = (tid & 15) * 8;  // 0..120

  for (int k0 = 0; k0 < K; k0 += 16) {
    __syncthreads();
    {
      const float* ap = A + (size_t)(bm + arow) * K + k0 + acol;
      float4 v0 = *reinterpret_cast<const float4*>(ap);
      float4 v1 = *reinterpret_cast<const float4*>(ap + 4);
      float vv[8] = {v0.x, v0.y, v0.z, v0.w, v1.x, v1.y, v1.z, v1.w};
#pragma unroll
      for (int i = 0; i < 8; i++) {
        unsigned hi = f2tf(vv[i]);
        Ah[arow][acol + i] = hi;
        Al[arow][acol + i] = f2tf(vv[i] - __uint_as_float(hi));
      }
    }
    {
      const float* bp = B + (size_t)(k0 + brow) * N + bn + bcol;
      float4 v0 = *reinterpret_cast<const float4*>(bp);
      float4 v1 = *reinterpret_cast<const float4*>(bp + 4);
      float vv[8] = {v0.x, v0.y, v0.z, v0.w, v1.x, v1.y, v1.z, v1.w};
#pragma unroll
      for (int i = 0; i < 8; i++) {
        unsigned hi = f2tf(vv[i]);
        Bh[brow][bcol + i] = hi;
        Bl[brow][bcol + i] = f2tf(vv[i] - __uint_as_float(hi));
      }
    }
    __syncthreads();

#pragma unroll
    for (int ks = 0; ks < 16; ks += 8) {
      unsigned ah[2][4], al[2][4];
#pragma unroll
      for (int mi = 0; mi < 2; mi++) {
        int r0 = wm * 32 + mi * 16 + g;
        ah[mi][0] = Ah[r0][ks + tg];         al[mi][0] = Al[r0][ks + tg];
        ah[mi][1] = Ah[r0 + 8][ks + tg];     al[mi][1] = Al[r0 + 8][ks + tg];
        ah[mi][2] = Ah[r0][ks + tg + 4];     al[mi][2] = Al[r0][ks + tg + 4];
        ah[mi][3] = Ah[r0 + 8][ks + tg + 4]; al[mi][3] = Al[r0 + 8][ks + tg + 4];
      }
#pragma unroll
      for (int ni = 0; ni < 8; ni++) {
        int c = wn * 64 + ni * 8 + g;
        unsigned bh0 = Bh[ks + tg][c], bh1 = Bh[ks + tg + 4][c];
        unsigned bl0 = Bl[ks + tg][c], bl1 = Bl[ks + tg + 4][c];
#pragma unroll
        for (int mi = 0; mi < 2; mi++) {
          mma_tf32(acc[mi][ni], ah[mi], bh0, bh1);   // hi*hi
          mma_tf32(acc[mi][ni], al[mi], bh0, bh1);   // lo*hi
          mma_tf32(acc[mi][ni], ah[mi], bl0, bl1);   // hi*lo
        }
      }
    }
  }

#pragma unroll
  for (int mi = 0; mi < 2; mi++) {
    int r0 = bm + wm * 32 + mi * 16 + g;
#pragma unroll
    for (int ni = 0; ni < 8; ni++) {
      int c = bn + wn * 64 + ni * 8 + tg * 2;
      C[(size_t)r0 * N + c]           = acc[mi][ni][0];
      C[(size_t)r0 * N + c + 1]       = acc[mi][ni][1];
      C[(size_t)(r0 + 8) * N + c]     = acc[mi][ni][2];
      C[(size_t)(r0 + 8) * N + c + 1] = acc[mi][ni][3];
    }
  }
}

// ---------------------------------------------------------------------------
// NeoX RoPE, in-place on g_qkv's Q (heads 0..31) and K (heads 32..39).
// One block per (t, head), 64 threads (one per rotation pair).
// ---------------------------------------------------------------------------
__global__ void rope_kernel(const int* __restrict__ positions) {
  const int bid = blockIdx.x;
  const int t  = bid / 40;
  const int hh = bid % 40;
  const int d  = threadIdx.x;  // 0..63

  const float pos = (float)positions[t];
  // inv_freq = theta^(-d/64) = exp(-(d/64) * ln(1e6))
  const float inv = expf(-((float)d * (1.0f / 64.0f)) * 13.815510557964274f);
  const float fr = pos * inv;
  float c, s;
  __sincosf(fr, &s, &c);
  // use accurate versions (sincosf precision); recompute accurately:
  c = cosf(fr);
  s = sinf(fr);

  float* base = g_qkv + (size_t)t * QKV_N + (hh < 32 ? hh * HD : HID + (hh - 32) * HD);
  const float x1 = base[d];
  const float x2 = base[d + 64];
  base[d]      = x1 * c - x2 * s;
  base[d + 64] = x2 * c + x1 * s;
}

// ---------------------------------------------------------------------------
// Flash attention: one block per (head, 64-row q tile). 128 threads = 4 warps,
// warp w owns q rows [w*16, w*16+16). Online softmax, 3xTF32 for S = Q K^T,
// single-tf32 for P V. P staged through SMEM (overlaying the K-hi tile) to
// convert the C-fragment layout into an A-fragment layout.
// ---------------------------------------------------------------------------
__global__ void attn_kernel(float* __restrict__ out) {
  extern __shared__ unsigned sm[];
  const int SQ = 64 * 132;
  unsigned* Qh = sm;
  unsigned* Ql = Qh + SQ;
  unsigned* Kh = Ql + SQ;
  unsigned* Kl = Kh + SQ;
  unsigned* Vs = Kl + SQ;
  unsigned* Ps = Kh;  // reused after S is computed; stride 68

  const int h   = blockIdx.x;        // 0..31
  const int qt  = blockIdx.y;        // 0..31
  const int kvh = h >> 2;            // GQA: 4 q heads per kv head
  const int q0  = qt * 64;
  const int tid = threadIdx.x;
  const int lane = tid & 31;
  const int w  = tid >> 5;
  const int g  = lane >> 2;
  const int tg = lane & 3;

  // Load Q tile (64 x 128), split hi/lo tf32
  for (int i = tid; i < 64 * 32; i += 128) {
    int r  = i >> 5;
    int c4 = (i & 31) * 4;
    float4 v = *reinterpret_cast<const float4*>(
        &g_qkv[(size_t)(q0 + r) * QKV_N + h * HD + c4]);
    float vv[4] = {v.x, v.y, v.z, v.w};
#pragma unroll
    for (int u = 0; u < 4; u++) {
      unsigned hi = f2tf(vv[u]);
      Qh[r * 132 + c4 + u] = hi;
      Ql[r * 132 + c4 + u] = f2tf(vv[u] - __uint_as_float(hi));
    }
  }

  float m0 = -1e30f, m1 = -1e30f, l0 = 0.f, l1 = 0.f;
  float O[16][4];
#pragma unroll
  for (int i = 0; i < 16; i++)
#pragma unroll
    for (int r = 0; r < 4; r++) O[i][r] = 0.f;

  for (int j = 0; j <= qt; ++j) {
    __syncthreads();  // previous iteration's P/V reads done before overwrite
    // Load K (hi/lo) and V (tf32) tiles for kv rows [j*64, j*64+64)
    for (int i = tid; i < 64 * 32; i += 128) {
      int r  = i >> 5;
      int c4 = (i & 31) * 4;
      const size_t base = (size_t)(j * 64 + r) * QKV_N + kvh * HD + c4;
      float4 kv = *reinterpret_cast<const float4*>(&g_qkv[base + 4096]);
      float4 vv = *reinterpret_cast<const float4*>(&g_qkv[base + 5120]);
      float ka[4] = {kv.x, kv.y, kv.z, kv.w};
      float va[4] = {vv.x, vv.y, vv.z, vv.w};
#pragma unroll
      for (int u = 0; u < 4; u++) {
        unsigned hi = f2tf(ka[u]);
        Kh[r * 132 + c4 + u] = hi;
        Kl[r * 132 + c4 + u] = f2tf(ka[u] - __uint_as_float(hi));
        Vs[r * 132 + c4 + u] = f2tf(va[u]);
      }
    }
    __syncthreads();

    // S = Q K^T (64x64 per block; 16x64 per warp), 3xTF32
    float s[8][4];
#pragma unroll
    for (int ni = 0; ni < 8; ni++)
#pragma unroll
      for (int r = 0; r < 4; r++) s[ni][r] = 0.f;

    const int ra = (w * 16 + g) * 132;
    const int rb = (w * 16 + g + 8) * 132;
#pragma unroll
    for (int d0 = 0; d0 < 128; d0 += 8) {
      unsigned qh[4], ql[4];
      qh[0] = Qh[ra + d0 + tg];     ql[0] = Ql[ra + d0 + tg];
      qh[1] = Qh[rb + d0 + tg];     ql[1] = Ql[rb + d0 + tg];
      qh[2] = Qh[ra + d0 + tg + 4]; ql[2] = Ql[ra + d0 + tg + 4];
      qh[3] = Qh[rb + d0 + tg + 4]; ql[3] = Ql[rb + d0 + tg + 4];
#pragma unroll
      for (int ni = 0; ni < 8; ni++) {
        int rn = (ni * 8 + g) * 132;
        unsigned kh0 = Kh[rn + d0 + tg], kh1 = Kh[rn + d0 + tg + 4];
        unsigned kl0 = Kl[rn + d0 + tg], kl1 = Kl[rn + d0 + tg + 4];
        mma_tf32(s[ni], qh, kh0, kh1);
        mma_tf32(s[ni], ql, kh0, kh1);
        mma_tf32(s[ni], qh, kl0, kl1);
      }
    }
    __syncthreads();  // everyone done reading Kh/Kl before P overlays it

    // Online softmax update
    const int gr0 = q0 + w * 16 + g;
    const int gr1 = gr0 + 8;
    float tm0 = -1e30f, tm1 = -1e30f;
#pragma unroll
    for (int ni = 0; ni < 8; ni++) {
#pragma unroll
      for (int cc = 0; cc < 2; cc++) {
        int gc = j * 64 + ni * 8 + tg * 2 + cc;
        float v0 = s[ni][cc] * ATTN_SCALE;
        float v1 = s[ni][2 + cc] * ATTN_SCALE;
        if (gc > gr0) v0 = -1e30f;
        if (gc > gr1) v1 = -1e30f;
        s[ni][cc] = v0;
        s[ni][2 + cc] = v1;
        tm0 = fmaxf(tm0, v0);
        tm1 = fmaxf(tm1, v1);
      }
    }
    tm0 = fmaxf(tm0, __shfl_xor_sync(0xffffffffu, tm0, 1));
    tm0 = fmaxf(tm0, __shfl_xor_sync(0xffffffffu, tm0, 2));
    tm1 = fmaxf(tm1, __shfl_xor_sync(0xffffffffu, tm1, 1));
    tm1 = fmaxf(tm1, __shfl_xor_sync(0xffffffffu, tm1, 2));

    float nm0 = fmaxf(m0, tm0), nm1 = fmaxf(m1, tm1);
    float a0 = expf(m0 - nm0), a1 = expf(m1 - nm1);

    const int pa = (w * 16 + g) * 68;
    const int pb = (w * 16 + g + 8) * 68;
    float ps0 = 0.f, ps1 = 0.f;
#pragma unroll
    for (int ni = 0; ni < 8; ni++) {
      float p00 = expf(s[ni][0] - nm0);
      float p01 = expf(s[ni][1] - nm0);
      float p10 = expf(s[ni][2] - nm1);
      float p11 = expf(s[ni][3] - nm1);
      ps0 += p00 + p01;
      ps1 += p10 + p11;
      Ps[pa + ni * 8 + tg * 2]     = f2tf(p00);
      Ps[pa + ni * 8 + tg * 2 + 1] = f2tf(p01);
      Ps[pb + ni * 8 + tg * 2]     = f2tf(p10);
      Ps[pb + ni * 8 + tg * 2 + 1] = f2tf(p11);
    }
    ps0 += __shfl_xor_sync(0xffffffffu, ps0, 1);
    ps0 += __shfl_xor_sync(0xffffffffu, ps0, 2);
    ps1 += __shfl_xor_sync(0xffffffffu, ps1, 1);
    ps1 += __shfl_xor_sync(0xffffffffu, ps1, 2);

    l0 = l0 * a0 + ps0;
    l1 = l1 * a1 + ps1;
    m0 = nm0;
    m1 = nm1;
#pragma unroll
    for (int ni = 0; ni < 16; ni++) {
      O[ni][0] *= a0; O[ni][1] *= a0;
      O[ni][2] *= a1; O[ni][3] *= a1;
    }
    __syncwarp();  // warp's P writes visible to its own PV reads

    // O += P V  (P: 16x64 per warp, V: 64x128)
#pragma unroll
    for (int kk = 0; kk < 64; kk += 8) {
      unsigned pf[4];
      pf[0] = Ps[pa + kk + tg];
      pf[1] = Ps[pb + kk + tg];
      pf[2] = Ps[pa + kk + tg + 4];
      pf[3] = Ps[pb + kk + tg + 4];
#pragma unroll
      for (int ni = 0; ni < 16; ni++) {
        unsigned b0 = Vs[(kk + tg) * 132 + ni * 8 + g];
        unsigned b1 = Vs[(kk + tg + 4) * 132 + ni * 8 + g];
        mma_tf32(O[ni], pf, b0, b1);
      }
    }
  }

  // Normalize and write out [T, 32*128]
  const float inv0 = 1.f / l0;
  const float inv1 = 1.f / l1;
  const int gr0 = q0 + w * 16 + g;
#pragma unroll
  for (int ni = 0; ni < 16; ni++) {
    int c = h * HD + ni * 8 + tg * 2;
    out[(size_t)gr0 * HID + c]           = O[ni][0] * inv0;
    out[(size_t)gr0 * HID + c + 1]       = O[ni][1] * inv0;
    out[(size_t)(gr0 + 8) * HID + c]     = O[ni][2] * inv1;
    out[(size_t)(gr0 + 8) * HID + c + 1] = O[ni][3] * inv1;
  }
}

// ---------------------------------------------------------------------------
// launch
// ---------------------------------------------------------------------------
extern "C" void kernel_launch(void* const* d_in, const int* in_sizes, int n_in,
                              void* d_out, int out_size) {
  (void)in_sizes; (void)n_in; (void)out_size;
  const int*   positions = (const int*)d_in[0];
  const float* hidden    = (const float*)d_in[1];
  const float* Wqkv      = (const float*)d_in[2];
  const float* Wo        = (const float*)d_in[3];
  float* out = (float*)d_out;

  float* qkv_p;
  float* attn_p;
  cudaGetSymbolAddress((void**)&qkv_p, g_qkv);
  cudaGetSymbolAddress((void**)&attn_p, g_attn);

  cudaFuncSetAttribute(attn_kernel, cudaFuncAttributeMaxDynamicSharedMemorySize,
                       ATTN_SMEM);

  // 1) QKV projection: [2048,4096] @ [4096,6144]
  gemm3_tf32<<<dim3(QKV_N / 128, T_SEQ / 128), 256>>>(hidden, Wqkv, qkv_p,
                                                      T_SEQ, QKV_N, HID);
  // 2) RoPE on Q + K (in place)
  rope_kernel<<<T_SEQ * 40, 64>>>(positions);
  // 3) Flash attention -> g_attn
  attn_kernel<<<dim3(NHEADS, T_SEQ / 64), 128, ATTN_SMEM>>>(attn_p);
  // 4) Output projection: [2048,4096] @ [4096,4096] -> d_out
  gemm3_tf32<<<dim3(HID / 128, T_SEQ / 128), 256>>>(attn_p, Wo, out,
                                                    T_SEQ, HID, HID);
}

// round 4
// speedup vs baseline: 1.0274x; 1.0274x over previous
#include <cuda_runtime.h>
#include <cstdint>

#define T_SEQ 2048
#define HID   4096
#define QKV_N 6144
#define HD    128
#define NHEADS 32
#define ATTN_SCALE 0.08838834764831845f   // 128^-0.5
#define ATTN_SMEM (5 * 64 * 132 * 4)

// GEMM tiling: BM=BN=128, BK=16, 3-stage cp.async pipeline.
// Per stage: 4 tiles (Ah,Al,Bh,Bl), each 128 rows x 80B (16 floats + 4 pad) = 10240B
#define STG_BYTES 40960
#define GEMM_SMEM (3 * STG_BYTES)

// Single dynamic-smem symbol for the whole TU (nvcc requirement)
extern __shared__ char dyn_smem[];

// ---------------------------------------------------------------------------
// Scratch (allocation-free rule: __device__ globals)
// ---------------------------------------------------------------------------
__device__ float g_qkv[(size_t)T_SEQ * QKV_N];   // QKV projection output
__device__ float g_attn[(size_t)T_SEQ * HID];    // attention output (pre-Wo)
__device__ float g_ah[(size_t)T_SEQ * HID];      // A hi (tf32-valued fp32)
__device__ float g_al[(size_t)T_SEQ * HID];      // A lo
__device__ float g_wqh[(size_t)QKV_N * HID];     // Wqkv^T hi  [N=6144, K=4096]
__device__ float g_wql[(size_t)QKV_N * HID];
__device__ float g_woh[(size_t)HID * HID];       // Wo^T hi    [N=4096, K=4096]
__device__ float g_wol[(size_t)HID * HID];

// ---------------------------------------------------------------------------
// helpers
// ---------------------------------------------------------------------------
__device__ __forceinline__ unsigned f2tf(float f) {
  unsigned u;
  asm("cvt.rna.tf32.f32 %0, %1;" : "=r"(u) : "f"(f));
  return u;
}

__device__ __forceinline__ uint32_t smem_u32(const void* p) {
  uint32_t a;
  asm("{ .reg .u64 t; cvta.to.shared.u64 t, %1; cvt.u32.u64 %0, t; }"
      : "=r"(a) : "l"(p));
  return a;
}

__device__ __forceinline__ void cp16(uint32_t dst, const float* src) {
  asm volatile("cp.async.cg.shared.global [%0], [%1], 16;"
               :: "r"(dst), "l"(src) : "memory");
}

__device__ __forceinline__ void ldsm4(unsigned r[4], uint32_t addr) {
  asm volatile("ldmatrix.sync.aligned.m8n8.x4.shared.b16 {%0,%1,%2,%3}, [%4];"
               : "=r"(r[0]), "=r"(r[1]), "=r"(r[2]), "=r"(r[3]) : "r"(addr));
}

__device__ __forceinline__ void mma_tf32(float d[4], const unsigned a[4],
                                         unsigned b0, unsigned b1) {
  asm volatile(
      "mma.sync.aligned.m16n8k8.row.col.f32.tf32.tf32.f32 "
      "{%0,%1,%2,%3}, {%4,%5,%6,%7}, {%8,%9}, {%0,%1,%2,%3};"
      : "+f"(d[0]), "+f"(d[1]), "+f"(d[2]), "+f"(d[3])
      : "r"(a[0]), "r"(a[1]), "r"(a[2]), "r"(a[3]), "r"(b0), "r"(b1));
}

// ---------------------------------------------------------------------------
// Prep kernels
// ---------------------------------------------------------------------------
__global__ void split_hilo(const float4* __restrict__ X, float4* __restrict__ Xh,
                           float4* __restrict__ Xl, int n4) {
  int i = blockIdx.x * 256 + threadIdx.x;
  if (i >= n4) return;
  float4 v = X[i];
  float4 h, l;
  h.x = __uint_as_float(f2tf(v.x)); l.x = __uint_as_float(f2tf(v.x - h.x));
  h.y = __uint_as_float(f2tf(v.y)); l.y = __uint_as_float(f2tf(v.y - h.y));
  h.z = __uint_as_float(f2tf(v.z)); l.z = __uint_as_float(f2tf(v.z - h.z));
  h.w = __uint_as_float(f2tf(v.w)); l.w = __uint_as_float(f2tf(v.w - h.w));
  Xh[i] = h;
  Xl[i] = l;
}

// W [K,N] row-major -> Wh/Wl [N,K] row-major (tf32-valued hi/lo)
__global__ void transpose_split(const float* __restrict__ W, float* __restrict__ Wh,
                                float* __restrict__ Wl, int K, int N) {
  __shared__ float t[32][33];
  const int n0 = blockIdx.x << 5, k0 = blockIdx.y << 5;
  const int tx = threadIdx.x, ty = threadIdx.y;  // 32 x 8
#pragma unroll
  for (int i = 0; i < 32; i += 8)
    t[ty + i][tx] = W[(size_t)(k0 + ty + i) * N + n0 + tx];
  __syncthreads();
#pragma unroll
  for (int i = 0; i < 32; i += 8) {
    float v = t[tx][ty + i];
    float hi = __uint_as_float(f2tf(v));
    size_t o = (size_t)(n0 + ty + i) * K + k0 + tx;
    Wh[o] = hi;
    Wl[o] = __uint_as_float(f2tf(v - hi));
  }
}

// ---------------------------------------------------------------------------
// 3xTF32 GEMM via ldmatrix + mma.sync, cp.async 3-stage pipeline.
// C[M,N] = A[M,K] @ B^T, A given as hi/lo [M,K], B as hi/lo [N,K].
// 256 threads = 8 warps (4x2), warp tile 32x64.
// ---------------------------------------------------------------------------
__global__ __launch_bounds__(256) void gemm_ldsm(
    const float* __restrict__ pAh, const float* __restrict__ pAl,
    const float* __restrict__ pBh, const float* __restrict__ pBl,
    float* __restrict__ C, int N, int K) {
  const uint32_t smb = smem_u32(dyn_smem);

  const int tid  = threadIdx.x;
  const int lane = tid & 31;
  const int warp = tid >> 5;
  const int wm = warp & 3;   // warp row 0..3 (32 M rows each)
  const int wn = warp >> 2;  // warp col 0..1 (64 N cols each)
  const int bm = blockIdx.y * 128;
  const int bn = blockIdx.x * 128;

  const float* aH = pAh + (size_t)bm * K;
  const float* aL = pAl + (size_t)bm * K;
  const float* bH = pBh + (size_t)bn * K;
  const float* bL = pBl + (size_t)bn * K;

  // cp.async mapping: thread -> (row, 32B half of the 64B data region)
  const int crow = tid >> 1;
  const int cqb  = (tid & 1) << 5;  // byte 0 or 32

  // ldmatrix lane offsets (pitch 80B rows, conflict-free)
  // A: quadrants of 16x8 tile
  const uint32_t aoff =
      (uint32_t)((wm * 32 + (lane & 7) + ((lane >> 3) & 1) * 8) * 80 +
                 ((lane >> 4) & 1) * 16);
  // B: [n][k] tile; q=lane>>3: {n0-7 k0-3, n0-7 k4-7, n8-15 k0-3, n8-15 k4-7}
  const uint32_t boff =
      (uint32_t)((wn * 64 + (lane & 7) + ((lane >> 4) & 1) * 8) * 80 +
                 ((lane >> 3) & 1) * 16);

  float acc[2][8][4];
#pragma unroll
  for (int i = 0; i < 2; i++)
#pragma unroll
    for (int j = 0; j < 8; j++)
#pragma unroll
      for (int r = 0; r < 4; r++) acc[i][j][r] = 0.f;

  const int NC = K >> 4;

#define ISSUE(c)                                                        \
  do {                                                                  \
    uint32_t sb = smb + (uint32_t)((c) % 3) * STG_BYTES;                \
    int k0 = (c) << 4;                                                  \
    uint32_t d = sb + (uint32_t)(crow * 80 + cqb);                      \
    size_t g = (size_t)crow * K + k0 + (cqb >> 2);                      \
    cp16(d,              aH + g); cp16(d + 16,         aH + g + 4);     \
    cp16(d + 10240,      aL + g); cp16(d + 10240 + 16, aL + g + 4);     \
    cp16(d + 20480,      bH + g); cp16(d + 20480 + 16, bH + g + 4);     \
    cp16(d + 30720,      bL + g); cp16(d + 30720 + 16, bL + g + 4);     \
    asm volatile("cp.async.commit_group;" ::: "memory");                \
  } while (0)

  ISSUE(0);
  ISSUE(1);

  for (int c = 0; c < NC; ++c) {
    asm volatile("cp.async.wait_group 1;" ::: "memory");
    __syncthreads();
    if (c + 2 < NC) ISSUE(c + 2);

    const uint32_t sb = smb + (uint32_t)(c % 3) * STG_BYTES;
    const uint32_t ab = sb + aoff;
    const uint32_t bb = sb + 20480 + boff;

#pragma unroll
    for (int ksb = 0; ksb <= 32; ksb += 32) {  // ks = 0, 8 -> byte 0, 32
      unsigned ah[2][4], al[2][4], bh[4][4], bl[4][4];
      ldsm4(ah[0], ab + ksb);
      ldsm4(ah[1], ab + 1280 + ksb);
      ldsm4(al[0], ab + 10240 + ksb);
      ldsm4(al[1], ab + 10240 + 1280 + ksb);
#pragma unroll
      for (int p = 0; p < 4; ++p) {
        ldsm4(bh[p], bb + p * 1280 + ksb);
        ldsm4(bl[p], bb + 10240 + p * 1280 + ksb);
      }
#pragma unroll
      for (int mi = 0; mi < 2; ++mi)
#pragma unroll
        for (int p = 0; p < 4; ++p)
#pragma unroll
          for (int sub = 0; sub < 2; ++sub) {
            const int ni = p * 2 + sub;
            mma_tf32(acc[mi][ni], ah[mi], bh[p][sub * 2], bh[p][sub * 2 + 1]);
            mma_tf32(acc[mi][ni], al[mi], bh[p][sub * 2], bh[p][sub * 2 + 1]);
            mma_tf32(acc[mi][ni], ah[mi], bl[p][sub * 2], bl[p][sub * 2 + 1]);
          }
    }
  }
#undef ISSUE

  const int g  = lane >> 2;
  const int tg = lane & 3;
#pragma unroll
  for (int mi = 0; mi < 2; mi++) {
    int r0 = bm + wm * 32 + mi * 16 + g;
#pragma unroll
    for (int ni = 0; ni < 8; ni++) {
      int c = bn + wn * 64 + ni * 8 + tg * 2;
      C[(size_t)r0 * N + c]           = acc[mi][ni][0];
      C[(size_t)r0 * N + c + 1]       = acc[mi][ni][1];
      C[(size_t)(r0 + 8) * N + c]     = acc[mi][ni][2];
      C[(size_t)(r0 + 8) * N + c + 1] = acc[mi][ni][3];
    }
  }
}

// ---------------------------------------------------------------------------
// NeoX RoPE, in-place on g_qkv's Q (heads 0..31) and K (heads 32..39).
// ---------------------------------------------------------------------------
__global__ void rope_kernel(const int* __restrict__ positions) {
  const int bid = blockIdx.x;
  const int t  = bid / 40;
  const int hh = bid % 40;
  const int d  = threadIdx.x;  // 0..63

  const float pos = (float)positions[t];
  const float inv = expf(-((float)d * (1.0f / 64.0f)) * 13.815510557964274f);
  const float fr = pos * inv;
  const float c = cosf(fr);
  const float s = sinf(fr);

  float* base = g_qkv + (size_t)t * QKV_N + (hh < 32 ? hh * HD : HID + (hh - 32) * HD);
  const float x1 = base[d];
  const float x2 = base[d + 64];
  base[d]      = x1 * c - x2 * s;
  base[d + 64] = x2 * c + x1 * s;
}

// ---------------------------------------------------------------------------
// Flash attention (round-1, proven: rel_err 2.8e-4)
// ---------------------------------------------------------------------------
__global__ void attn_kernel(float* __restrict__ out) {
  unsigned* sm = reinterpret_cast<unsigned*>(dyn_smem);
  const int SQ = 64 * 132;
  unsigned* Qh = sm;
  unsigned* Ql = Qh + SQ;
  unsigned* Kh = Ql + SQ;
  unsigned* Kl = Kh + SQ;
  unsigned* Vs = Kl + SQ;
  unsigned* Ps = Kh;  // reused after S; stride 68

  const int h   = blockIdx.x;
  const int qt  = blockIdx.y;
  const int kvh = h >> 2;
  const int q0  = qt * 64;
  const int tid = threadIdx.x;
  const int lane = tid & 31;
  const int w  = tid >> 5;
  const int g  = lane >> 2;
  const int tg = lane & 3;

  for (int i = tid; i < 64 * 32; i += 128) {
    int r  = i >> 5;
    int c4 = (i & 31) * 4;
    float4 v = *reinterpret_cast<const float4*>(
        &g_qkv[(size_t)(q0 + r) * QKV_N + h * HD + c4]);
    float vv[4] = {v.x, v.y, v.z, v.w};
#pragma unroll
    for (int u = 0; u < 4; u++) {
      unsigned hi = f2tf(vv[u]);
      Qh[r * 132 + c4 + u] = hi;
      Ql[r * 132 + c4 + u] = f2tf(vv[u] - __uint_as_float(hi));
    }
  }

  float m0 = -1e30f, m1 = -1e30f, l0 = 0.f, l1 = 0.f;
  float O[16][4];
#pragma unroll
  for (int i = 0; i < 16; i++)
#pragma unroll
    for (int r = 0; r < 4; r++) O[i][r] = 0.f;

  for (int j = 0; j <= qt; ++j) {
    __syncthreads();
    for (int i = tid; i < 64 * 32; i += 128) {
      int r  = i >> 5;
      int c4 = (i & 31) * 4;
      const size_t base = (size_t)(j * 64 + r) * QKV_N + kvh * HD + c4;
      float4 kv = *reinterpret_cast<const float4*>(&g_qkv[base + 4096]);
      float4 vv = *reinterpret_cast<const float4*>(&g_qkv[base + 5120]);
      float ka[4] = {kv.x, kv.y, kv.z, kv.w};
      float va[4] = {vv.x, vv.y, vv.z, vv.w};
#pragma unroll
      for (int u = 0; u < 4; u++) {
        unsigned hi = f2tf(ka[u]);
        Kh[r * 132 + c4 + u] = hi;
        Kl[r * 132 + c4 + u] = f2tf(ka[u] - __uint_as_float(hi));
        Vs[r * 132 + c4 + u] = f2tf(va[u]);
      }
    }
    __syncthreads();

    float s[8][4];
#pragma unroll
    for (int ni = 0; ni < 8; ni++)
#pragma unroll
      for (int r = 0; r < 4; r++) s[ni][r] = 0.f;

    const int ra = (w * 16 + g) * 132;
    const int rb = (w * 16 + g + 8) * 132;
#pragma unroll
    for (int d0 = 0; d0 < 128; d0 += 8) {
      unsigned qh[4], ql[4];
      qh[0] = Qh[ra + d0 + tg];     ql[0] = Ql[ra + d0 + tg];
      qh[1] = Qh[rb + d0 + tg];     ql[1] = Ql[rb + d0 + tg];
      qh[2] = Qh[ra + d0 + tg + 4]; ql[2] = Ql[ra + d0 + tg + 4];
      qh[3] = Qh[rb + d0 + tg + 4]; ql[3] = Ql[rb + d0 + tg + 4];
#pragma unroll
      for (int ni = 0; ni < 8; ni++) {
        int rn = (ni * 8 + g) * 132;
        unsigned kh0 = Kh[rn + d0 + tg], kh1 = Kh[rn + d0 + tg + 4];
        unsigned kl0 = Kl[rn + d0 + tg], kl1 = Kl[rn + d0 + tg + 4];
        mma_tf32(s[ni], qh, kh0, kh1);
        mma_tf32(s[ni], ql, kh0, kh1);
        mma_tf32(s[ni], qh, kl0, kl1);
      }
    }
    __syncthreads();

    const int gr0 = q0 + w * 16 + g;
    const int gr1 = gr0 + 8;
    float tm0 = -1e30f, tm1 = -1e30f;
#pragma unroll
    for (int ni = 0; ni < 8; ni++) {
#pragma unroll
      for (int cc = 0; cc < 2; cc++) {
        int gc = j * 64 + ni * 8 + tg * 2 + cc;
        float v0 = s[ni][cc] * ATTN_SCALE;
        float v1 = s[ni][2 + cc] * ATTN_SCALE;
        if (gc > gr0) v0 = -1e30f;
        if (gc > gr1) v1 = -1e30f;
        s[ni][cc] = v0;
        s[ni][2 + cc] = v1;
        tm0 = fmaxf(tm0, v0);
        tm1 = fmaxf(tm1, v1);
      }
    }
    tm0 = fmaxf(tm0, __shfl_xor_sync(0xffffffffu, tm0, 1));
    tm0 = fmaxf(tm0, __shfl_xor_sync(0xffffffffu, tm0, 2));
    tm1 = fmaxf(tm1, __shfl_xor_sync(0xffffffffu, tm1, 1));
    tm1 = fmaxf(tm1, __shfl_xor_sync(0xffffffffu, tm1, 2));

    float nm0 = fmaxf(m0, tm0), nm1 = fmaxf(m1, tm1);
    float a0 = expf(m0 - nm0), a1 = expf(m1 - nm1);

    const int pa = (w * 16 + g) * 68;
    const int pb = (w * 16 + g + 8) * 68;
    float ps0 = 0.f, ps1 = 0.f;
#pragma unroll
    for (int ni = 0; ni < 8; ni++) {
      float p00 = expf(s[ni][0] - nm0);
      float p01 = expf(s[ni][1] - nm0);
      float p10 = expf(s[ni][2] - nm1);
      float p11 = expf(s[ni][3] - nm1);
      ps0 += p00 + p01;
      ps1 += p10 + p11;
      Ps[pa + ni * 8 + tg * 2]     = f2tf(p00);
      Ps[pa + ni * 8 + tg * 2 + 1] = f2tf(p01);
      Ps[pb + ni * 8 + tg * 2]     = f2tf(p10);
      Ps[pb + ni * 8 + tg * 2 + 1] = f2tf(p11);
    }
    ps0 += __shfl_xor_sync(0xffffffffu, ps0, 1);
    ps0 += __shfl_xor_sync(0xffffffffu, ps0, 2);
    ps1 += __shfl_xor_sync(0xffffffffu, ps1, 1);
    ps1 += __shfl_xor_sync(0xffffffffu, ps1, 2);

    l0 = l0 * a0 + ps0;
    l1 = l1 * a1 + ps1;
    m0 = nm0;
    m1 = nm1;
#pragma unroll
    for (int ni = 0; ni < 16; ni++) {
      O[ni][0] *= a0; O[ni][1] *= a0;
      O[ni][2] *= a1; O[ni][3] *= a1;
    }
    __syncwarp();

#pragma unroll
    for (int kk = 0; kk < 64; kk += 8) {
      unsigned pf[4];
      pf[0] = Ps[pa + kk + tg];
      pf[1] = Ps[pb + kk + tg];
      pf[2] = Ps[pa + kk + tg + 4];
      pf[3] = Ps[pb + kk + tg + 4];
#pragma unroll
      for (int ni = 0; ni < 16; ni++) {
        unsigned b0 = Vs[(kk + tg) * 132 + ni * 8 + g];
        unsigned b1 = Vs[(kk + tg + 4) * 132 + ni * 8 + g];
        mma_tf32(O[ni], pf, b0, b1);
      }
    }
  }

  const float inv0 = 1.f / l0;
  const float inv1 = 1.f / l1;
  const int gr0 = q0 + w * 16 + g;
#pragma unroll
  for (int ni = 0; ni < 16; ni++) {
    int c = h * HD + ni * 8 + tg * 2;
    out[(size_t)gr0 * HID + c]           = O[ni][0] * inv0;
    out[(size_t)gr0 * HID + c + 1]       = O[ni][1] * inv0;
    out[(size_t)(gr0 + 8) * HID + c]     = O[ni][2] * inv1;
    out[(size_t)(gr0 + 8) * HID + c + 1] = O[ni][3] * inv1;
  }
}

// ---------------------------------------------------------------------------
// launch
// ---------------------------------------------------------------------------
extern "C" void kernel_launch(void* const* d_in, const int* in_sizes, int n_in,
                              void* d_out, int out_size) {
  (void)in_sizes; (void)n_in; (void)out_size;
  const int*   positions = (const int*)d_in[0];
  const float* hidden    = (const float*)d_in[1];
  const float* Wqkv      = (const float*)d_in[2];
  const float* Wo        = (const float*)d_in[3];
  float* out = (float*)d_out;

  float *qkv_p, *attn_p, *ah, *al, *wqh, *wql, *woh, *wol;
  cudaGetSymbolAddress((void**)&qkv_p, g_qkv);
  cudaGetSymbolAddress((void**)&attn_p, g_attn);
  cudaGetSymbolAddress((void**)&ah, g_ah);
  cudaGetSymbolAddress((void**)&al, g_al);
  cudaGetSymbolAddress((void**)&wqh, g_wqh);
  cudaGetSymbolAddress((void**)&wql, g_wql);
  cudaGetSymbolAddress((void**)&woh, g_woh);
  cudaGetSymbolAddress((void**)&wol, g_wol);

  cudaFuncSetAttribute(attn_kernel, cudaFuncAttributeMaxDynamicSharedMemorySize,
                       ATTN_SMEM);
  cudaFuncSetAttribute(gemm_ldsm, cudaFuncAttributeMaxDynamicSharedMemorySize,
                       GEMM_SMEM);

  // Prep: transpose+split weights, split activations
  transpose_split<<<dim3(QKV_N / 32, HID / 32), dim3(32, 8)>>>(Wqkv, wqh, wql,
                                                               HID, QKV_N);
  transpose_split<<<dim3(HID / 32, HID / 32), dim3(32, 8)>>>(Wo, woh, wol,
                                                             HID, HID);
  split_hilo<<<(T_SEQ * HID / 4 + 255) / 256, 256>>>(
      (const float4*)hidden, (float4*)ah, (float4*)al, T_SEQ * HID / 4);

  // 1) QKV projection
  gemm_ldsm<<<dim3(QKV_N / 128, T_SEQ / 128), 256, GEMM_SMEM>>>(
      ah, al, wqh, wql, qkv_p, QKV_N, HID);
  // 2) RoPE
  rope_kernel<<<T_SEQ * 40, 64>>>(positions);
  // 3) Flash attention
  attn_kernel<<<dim3(NHEADS, T_SEQ / 64), 128, ATTN_SMEM>>>(attn_p);
  // 4) Output projection
  split_hilo<<<(T_SEQ * HID / 4 + 255) / 256, 256>>>(
      (const float4*)attn_p, (float4*)ah, (float4*)al, T_SEQ * HID / 4);
  gemm_ldsm<<<dim3(HID / 128, T_SEQ / 128), 256, GEMM_SMEM>>>(
      ah, al, woh, wol, out, HID, HID);
}

// round 5
// speedup vs baseline: 1.5350x; 1.4941x over previous
#include <cuda_runtime.h>
#include <cstdint>

#define T_SEQ 2048
#define HID   4096
#define QKV_N 6144
#define HD    128
#define NHEADS 32
#define ATTN_SCALE 0.08838834764831845f   // 128^-0.5
#define ATTN_SMEM (5 * 64 * 132 * 4)

// GEMM tiling: BM=BN=128, BK=16, 3-stage cp.async pipeline, 2 CTAs/SM.
// Per stage: 3 tiles (Ah,Al,Bh), each 128 rows x 80B (16 floats + 4 pad)
#define TILE_BYTES 10240
#define STG_BYTES (3 * TILE_BYTES)
#define GEMM_SMEM (3 * STG_BYTES)

// Single dynamic-smem symbol for the whole TU (nvcc requirement)
extern __shared__ char dyn_smem[];

// ---------------------------------------------------------------------------
// Scratch (allocation-free rule: __device__ globals)
// ---------------------------------------------------------------------------
__device__ float g_qkv[(size_t)T_SEQ * QKV_N];   // QKV projection output
__device__ float g_attn[(size_t)T_SEQ * HID];    // attention output (pre-Wo)
__device__ float g_ah[(size_t)T_SEQ * HID];      // A hi (tf32-valued fp32)
__device__ float g_al[(size_t)T_SEQ * HID];      // A lo
__device__ float g_wqh[(size_t)QKV_N * HID];     // Wqkv^T hi  [N=6144, K=4096]
__device__ float g_woh[(size_t)HID * HID];       // Wo^T hi    [N=4096, K=4096]

// ---------------------------------------------------------------------------
// helpers
// ---------------------------------------------------------------------------
__device__ __forceinline__ unsigned f2tf(float f) {
  unsigned u;
  asm("cvt.rna.tf32.f32 %0, %1;" : "=r"(u) : "f"(f));
  return u;
}

__device__ __forceinline__ uint32_t smem_u32(const void* p) {
  uint32_t a;
  asm("{ .reg .u64 t; cvta.to.shared.u64 t, %1; cvt.u32.u64 %0, t; }"
      : "=r"(a) : "l"(p));
  return a;
}

__device__ __forceinline__ void cp16(uint32_t dst, const float* src) {
  asm volatile("cp.async.cg.shared.global [%0], [%1], 16;"
               :: "r"(dst), "l"(src) : "memory");
}

__device__ __forceinline__ void ldsm4(unsigned r[4], uint32_t addr) {
  asm volatile("ldmatrix.sync.aligned.m8n8.x4.shared.b16 {%0,%1,%2,%3}, [%4];"
               : "=r"(r[0]), "=r"(r[1]), "=r"(r[2]), "=r"(r[3]) : "r"(addr));
}

__device__ __forceinline__ void mma_tf32(float d[4], const unsigned a[4],
                                         unsigned b0, unsigned b1) {
  asm volatile(
      "mma.sync.aligned.m16n8k8.row.col.f32.tf32.tf32.f32 "
      "{%0,%1,%2,%3}, {%4,%5,%6,%7}, {%8,%9}, {%0,%1,%2,%3};"
      : "+f"(d[0]), "+f"(d[1]), "+f"(d[2]), "+f"(d[3])
      : "r"(a[0]), "r"(a[1]), "r"(a[2]), "r"(a[3]), "r"(b0), "r"(b1));
}

// ---------------------------------------------------------------------------
// Prep kernels
// ---------------------------------------------------------------------------
__global__ void split_hilo(const float4* __restrict__ X, float4* __restrict__ Xh,
                           float4* __restrict__ Xl, int n4) {
  int i = blockIdx.x * 256 + threadIdx.x;
  if (i >= n4) return;
  float4 v = X[i];
  float4 h, l;
  h.x = __uint_as_float(f2tf(v.x)); l.x = __uint_as_float(f2tf(v.x - h.x));
  h.y = __uint_as_float(f2tf(v.y)); l.y = __uint_as_float(f2tf(v.y - h.y));
  h.z = __uint_as_float(f2tf(v.z)); l.z = __uint_as_float(f2tf(v.z - h.z));
  h.w = __uint_as_float(f2tf(v.w)); l.w = __uint_as_float(f2tf(v.w - h.w));
  Xh[i] = h;
  Xl[i] = l;
}

// W [K,N] row-major -> Wh [N,K] row-major (tf32-valued hi only)
__global__ void transpose_split(const float* __restrict__ W, float* __restrict__ Wh,
                                int K, int N) {
  __shared__ float t[32][33];
  const int n0 = blockIdx.x << 5, k0 = blockIdx.y << 5;
  const int tx = threadIdx.x, ty = threadIdx.y;  // 32 x 8
#pragma unroll
  for (int i = 0; i < 32; i += 8)
    t[ty + i][tx] = W[(size_t)(k0 + ty + i) * N + n0 + tx];
  __syncthreads();
#pragma unroll
  for (int i = 0; i < 32; i += 8) {
    float v = t[tx][ty + i];
    Wh[(size_t)(n0 + ty + i) * K + k0 + tx] = __uint_as_float(f2tf(v));
  }
}

// ---------------------------------------------------------------------------
// 2xTF32 GEMM via ldmatrix + mma.sync, cp.async 3-stage pipeline, 2 CTAs/SM.
// C = A @ tf32(B)^T:  terms Ah*Bh + Al*Bh  (== full-precision A times tf32 B).
// A given as hi/lo [M,K], B as hi [N,K]. 256 threads = 8 warps, warp 32x64.
// ---------------------------------------------------------------------------
__global__ __launch_bounds__(256, 2) void gemm_ldsm(
    const float* __restrict__ pAh, const float* __restrict__ pAl,
    const float* __restrict__ pBh, float* __restrict__ C, int N, int K) {
  const uint32_t smb = smem_u32(dyn_smem);

  const int tid  = threadIdx.x;
  const int lane = tid & 31;
  const int warp = tid >> 5;
  const int wm = warp & 3;   // warp row 0..3 (32 M rows each)
  const int wn = warp >> 2;  // warp col 0..1 (64 N cols each)
  const int bm = blockIdx.y * 128;
  const int bn = blockIdx.x * 128;

  const float* aH = pAh + (size_t)bm * K;
  const float* aL = pAl + (size_t)bm * K;
  const float* bH = pBh + (size_t)bn * K;

  // cp.async mapping: thread -> (row, 32B half of the 64B data region)
  const int crow = tid >> 1;
  const int cqb  = (tid & 1) << 5;  // byte 0 or 32

  // ldmatrix lane offsets (pitch 80B rows, conflict-free)
  const uint32_t aoff =
      (uint32_t)((wm * 32 + (lane & 7) + ((lane >> 3) & 1) * 8) * 80 +
                 ((lane >> 4) & 1) * 16);
  const uint32_t boff =
      (uint32_t)((wn * 64 + (lane & 7) + ((lane >> 4) & 1) * 8) * 80 +
                 ((lane >> 3) & 1) * 16);

  float acc[2][8][4];
#pragma unroll
  for (int i = 0; i < 2; i++)
#pragma unroll
    for (int j = 0; j < 8; j++)
#pragma unroll
      for (int r = 0; r < 4; r++) acc[i][j][r] = 0.f;

  const int NC = K >> 4;

#define ISSUE(c)                                                        \
  do {                                                                  \
    uint32_t sb = smb + (uint32_t)((c) % 3) * STG_BYTES;                \
    int k0 = (c) << 4;                                                  \
    uint32_t d = sb + (uint32_t)(crow * 80 + cqb);                      \
    size_t g = (size_t)crow * K + k0 + (cqb >> 2);                      \
    cp16(d,                  aH + g); cp16(d + 16,                  aH + g + 4); \
    cp16(d + TILE_BYTES,     aL + g); cp16(d + TILE_BYTES + 16,     aL + g + 4); \
    cp16(d + 2 * TILE_BYTES, bH + g); cp16(d + 2 * TILE_BYTES + 16, bH + g + 4); \
    asm volatile("cp.async.commit_group;" ::: "memory");                \
  } while (0)

  ISSUE(0);
  ISSUE(1);

  for (int c = 0; c < NC; ++c) {
    asm volatile("cp.async.wait_group 1;" ::: "memory");
    __syncthreads();
    if (c + 2 < NC) ISSUE(c + 2);

    const uint32_t sb = smb + (uint32_t)(c % 3) * STG_BYTES;
    const uint32_t ab = sb + aoff;
    const uint32_t bb = sb + 2 * TILE_BYTES + boff;

#pragma unroll
    for (int ksb = 0; ksb <= 32; ksb += 32) {  // ks = 0, 8 -> byte 0, 32
      unsigned ah[2][4], al[2][4], bh[4][4];
      ldsm4(ah[0], ab + ksb);
      ldsm4(ah[1], ab + 1280 + ksb);
      ldsm4(al[0], ab + TILE_BYTES + ksb);
      ldsm4(al[1], ab + TILE_BYTES + 1280 + ksb);
#pragma unroll
      for (int p = 0; p < 4; ++p) ldsm4(bh[p], bb + p * 1280 + ksb);
#pragma unroll
      for (int mi = 0; mi < 2; ++mi)
#pragma unroll
        for (int p = 0; p < 4; ++p)
#pragma unroll
          for (int sub = 0; sub < 2; ++sub) {
            const int ni = p * 2 + sub;
            mma_tf32(acc[mi][ni], ah[mi], bh[p][sub * 2], bh[p][sub * 2 + 1]);
            mma_tf32(acc[mi][ni], al[mi], bh[p][sub * 2], bh[p][sub * 2 + 1]);
          }
    }
  }
#undef ISSUE

  const int g  = lane >> 2;
  const int tg = lane & 3;
#pragma unroll
  for (int mi = 0; mi < 2; mi++) {
    int r0 = bm + wm * 32 + mi * 16 + g;
#pragma unroll
    for (int ni = 0; ni < 8; ni++) {
      int c = bn + wn * 64 + ni * 8 + tg * 2;
      C[(size_t)r0 * N + c]           = acc[mi][ni][0];
      C[(size_t)r0 * N + c + 1]       = acc[mi][ni][1];
      C[(size_t)(r0 + 8) * N + c]     = acc[mi][ni][2];
      C[(size_t)(r0 + 8) * N + c + 1] = acc[mi][ni][3];
    }
  }
}

// ---------------------------------------------------------------------------
// NeoX RoPE, in-place on g_qkv's Q (heads 0..31) and K (heads 32..39).
// ---------------------------------------------------------------------------
__global__ void rope_kernel(const int* __restrict__ positions) {
  const int bid = blockIdx.x;
  const int t  = bid / 40;
  const int hh = bid % 40;
  const int d  = threadIdx.x;  // 0..63

  const float pos = (float)positions[t];
  const float inv = expf(-((float)d * (1.0f / 64.0f)) * 13.815510557964274f);
  const float fr = pos * inv;
  const float c = cosf(fr);
  const float s = sinf(fr);

  float* base = g_qkv + (size_t)t * QKV_N + (hh < 32 ? hh * HD : HID + (hh - 32) * HD);
  const float x1 = base[d];
  const float x2 = base[d + 64];
  base[d]      = x1 * c - x2 * s;
  base[d + 64] = x2 * c + x1 * s;
}

// ---------------------------------------------------------------------------
// Flash attention (round-1, proven: rel_err 2.8e-4)
// ---------------------------------------------------------------------------
__global__ void attn_kernel(float* __restrict__ out) {
  unsigned* sm = reinterpret_cast<unsigned*>(dyn_smem);
  const int SQ = 64 * 132;
  unsigned* Qh = sm;
  unsigned* Ql = Qh + SQ;
  unsigned* Kh = Ql + SQ;
  unsigned* Kl = Kh + SQ;
  unsigned* Vs = Kl + SQ;
  unsigned* Ps = Kh;  // reused after S; stride 68

  const int h   = blockIdx.x;
  const int qt  = blockIdx.y;
  const int kvh = h >> 2;
  const int q0  = qt * 64;
  const int tid = threadIdx.x;
  const int lane = tid & 31;
  const int w  = tid >> 5;
  const int g  = lane >> 2;
  const int tg = lane & 3;

  for (int i = tid; i < 64 * 32; i += 128) {
    int r  = i >> 5;
    int c4 = (i & 31) * 4;
    float4 v = *reinterpret_cast<const float4*>(
        &g_qkv[(size_t)(q0 + r) * QKV_N + h * HD + c4]);
    float vv[4] = {v.x, v.y, v.z, v.w};
#pragma unroll
    for (int u = 0; u < 4; u++) {
      unsigned hi = f2tf(vv[u]);
      Qh[r * 132 + c4 + u] = hi;
      Ql[r * 132 + c4 + u] = f2tf(vv[u] - __uint_as_float(hi));
    }
  }

  float m0 = -1e30f, m1 = -1e30f, l0 = 0.f, l1 = 0.f;
  float O[16][4];
#pragma unroll
  for (int i = 0; i < 16; i++)
#pragma unroll
    for (int r = 0; r < 4; r++) O[i][r] = 0.f;

  for (int j = 0; j <= qt; ++j) {
    __syncthreads();
    for (int i = tid; i < 64 * 32; i += 128) {
      int r  = i >> 5;
      int c4 = (i & 31) * 4;
      const size_t base = (size_t)(j * 64 + r) * QKV_N + kvh * HD + c4;
      float4 kv = *reinterpret_cast<const float4*>(&g_qkv[base + 4096]);
      float4 vv = *reinterpret_cast<const float4*>(&g_qkv[base + 5120]);
      float ka[4] = {kv.x, kv.y, kv.z, kv.w};
      float va[4] = {vv.x, vv.y, vv.z, vv.w};
#pragma unroll
      for (int u = 0; u < 4; u++) {
        unsigned hi = f2tf(ka[u]);
        Kh[r * 132 + c4 + u] = hi;
        Kl[r * 132 + c4 + u] = f2tf(ka[u] - __uint_as_float(hi));
        Vs[r * 132 + c4 + u] = f2tf(va[u]);
      }
    }
    __syncthreads();

    float s[8][4];
#pragma unroll
    for (int ni = 0; ni < 8; ni++)
#pragma unroll
      for (int r = 0; r < 4; r++) s[ni][r] = 0.f;

    const int ra = (w * 16 + g) * 132;
    const int rb = (w * 16 + g + 8) * 132;
#pragma unroll
    for (int d0 = 0; d0 < 128; d0 += 8) {
      unsigned qh[4], ql[4];
      qh[0] = Qh[ra + d0 + tg];     ql[0] = Ql[ra + d0 + tg];
      qh[1] = Qh[rb + d0 + tg];     ql[1] = Ql[rb + d0 + tg];
      qh[2] = Qh[ra + d0 + tg + 4]; ql[2] = Ql[ra + d0 + tg + 4];
      qh[3] = Qh[rb + d0 + tg + 4]; ql[3] = Ql[rb + d0 + tg + 4];
#pragma unroll
      for (int ni = 0; ni < 8; ni++) {
        int rn = (ni * 8 + g) * 132;
        unsigned kh0 = Kh[rn + d0 + tg], kh1 = Kh[rn + d0 + tg + 4];
        unsigned kl0 = Kl[rn + d0 + tg], kl1 = Kl[rn + d0 + tg + 4];
        mma_tf32(s[ni], qh, kh0, kh1);
        mma_tf32(s[ni], ql, kh0, kh1);
        mma_tf32(s[ni], qh, kl0, kl1);
      }
    }
    __syncthreads();

    const int gr0 = q0 + w * 16 + g;
    const int gr1 = gr0 + 8;
    float tm0 = -1e30f, tm1 = -1e30f;
#pragma unroll
    for (int ni = 0; ni < 8; ni++) {
#pragma unroll
      for (int cc = 0; cc < 2; cc++) {
        int gc = j * 64 + ni * 8 + tg * 2 + cc;
        float v0 = s[ni][cc] * ATTN_SCALE;
        float v1 = s[ni][2 + cc] * ATTN_SCALE;
        if (gc > gr0) v0 = -1e30f;
        if (gc > gr1) v1 = -1e30f;
        s[ni][cc] = v0;
        s[ni][2 + cc] = v1;
        tm0 = fmaxf(tm0, v0);
        tm1 = fmaxf(tm1, v1);
      }
    }
    tm0 = fmaxf(tm0, __shfl_xor_sync(0xffffffffu, tm0, 1));
    tm0 = fmaxf(tm0, __shfl_xor_sync(0xffffffffu, tm0, 2));
    tm1 = fmaxf(tm1, __shfl_xor_sync(0xffffffffu, tm1, 1));
    tm1 = fmaxf(tm1, __shfl_xor_sync(0xffffffffu, tm1, 2));

    float nm0 = fmaxf(m0, tm0), nm1 = fmaxf(m1, tm1);
    float a0 = expf(m0 - nm0), a1 = expf(m1 - nm1);

    const int pa = (w * 16 + g) * 68;
    const int pb = (w * 16 + g + 8) * 68;
    float ps0 = 0.f, ps1 = 0.f;
#pragma unroll
    for (int ni = 0; ni < 8; ni++) {
      float p00 = expf(s[ni][0] - nm0);
      float p01 = expf(s[ni][1] - nm0);
      float p10 = expf(s[ni][2] - nm1);
      float p11 = expf(s[ni][3] - nm1);
      ps0 += p00 + p01;
      ps1 += p10 + p11;
      Ps[pa + ni * 8 + tg * 2]     = f2tf(p00);
      Ps[pa + ni * 8 + tg * 2 + 1] = f2tf(p01);
      Ps[pb + ni * 8 + tg * 2]     = f2tf(p10);
      Ps[pb + ni * 8 + tg * 2 + 1] = f2tf(p11);
    }
    ps0 += __shfl_xor_sync(0xffffffffu, ps0, 1);
    ps0 += __shfl_xor_sync(0xffffffffu, ps0, 2);
    ps1 += __shfl_xor_sync(0xffffffffu, ps1, 1);
    ps1 += __shfl_xor_sync(0xffffffffu, ps1, 2);

    l0 = l0 * a0 + ps0;
    l1 = l1 * a1 + ps1;
    m0 = nm0;
    m1 = nm1;
#pragma unroll
    for (int ni = 0; ni < 16; ni++) {
      O[ni][0] *= a0; O[ni][1] *= a0;
      O[ni][2] *= a1; O[ni][3] *= a1;
    }
    __syncwarp();

#pragma unroll
    for (int kk = 0; kk < 64; kk += 8) {
      unsigned pf[4];
      pf[0] = Ps[pa + kk + tg];
      pf[1] = Ps[pb + kk + tg];
      pf[2] = Ps[pa + kk + tg + 4];
      pf[3] = Ps[pb + kk + tg + 4];
#pragma unroll
      for (int ni = 0; ni < 16; ni++) {
        unsigned b0 = Vs[(kk + tg) * 132 + ni * 8 + g];
        unsigned b1 = Vs[(kk + tg + 4) * 132 + ni * 8 + g];
        mma_tf32(O[ni], pf, b0, b1);
      }
    }
  }

  const float inv0 = 1.f / l0;
  const float inv1 = 1.f / l1;
  const int gr0 = q0 + w * 16 + g;
#pragma unroll
  for (int ni = 0; ni < 16; ni++) {
    int c = h * HD + ni * 8 + tg * 2;
    out[(size_t)gr0 * HID + c]           = O[ni][0] * inv0;
    out[(size_t)gr0 * HID + c + 1]       = O[ni][1] * inv0;
    out[(size_t)(gr0 + 8) * HID + c]     = O[ni][2] * inv1;
    out[(size_t)(gr0 + 8) * HID + c + 1] = O[ni][3] * inv1;
  }
}

// ---------------------------------------------------------------------------
// launch
// ---------------------------------------------------------------------------
extern "C" void kernel_launch(void* const* d_in, const int* in_sizes, int n_in,
                              void* d_out, int out_size) {
  (void)in_sizes; (void)n_in; (void)out_size;
  const int*   positions = (const int*)d_in[0];
  const float* hidden    = (const float*)d_in[1];
  const float* Wqkv      = (const float*)d_in[2];
  const float* Wo        = (const float*)d_in[3];
  float* out = (float*)d_out;

  float *qkv_p, *attn_p, *ah, *al, *wqh, *woh;
  cudaGetSymbolAddress((void**)&qkv_p, g_qkv);
  cudaGetSymbolAddress((void**)&attn_p, g_attn);
  cudaGetSymbolAddress((void**)&ah, g_ah);
  cudaGetSymbolAddress((void**)&al, g_al);
  cudaGetSymbolAddress((void**)&wqh, g_wqh);
  cudaGetSymbolAddress((void**)&woh, g_woh);

  cudaFuncSetAttribute(attn_kernel, cudaFuncAttributeMaxDynamicSharedMemorySize,
                       ATTN_SMEM);
  cudaFuncSetAttribute(gemm_ldsm, cudaFuncAttributeMaxDynamicSharedMemorySize,
                       GEMM_SMEM);

  // Prep: transpose weights (tf32 hi only), split activations hi/lo
  transpose_split<<<dim3(QKV_N / 32, HID / 32), dim3(32, 8)>>>(Wqkv, wqh,
                                                               HID, QKV_N);
  transpose_split<<<dim3(HID / 32, HID / 32), dim3(32, 8)>>>(Wo, woh,
                                                             HID, HID);
  split_hilo<<<(T_SEQ * HID / 4 + 255) / 256, 256>>>(
      (const float4*)hidden, (float4*)ah, (float4*)al, T_SEQ * HID / 4);

  // 1) QKV projection
  gemm_ldsm<<<dim3(QKV_N / 128, T_SEQ / 128), 256, GEMM_SMEM>>>(
      ah, al, wqh, qkv_p, QKV_N, HID);
  // 2) RoPE
  rope_kernel<<<T_SEQ * 40, 64>>>(positions);
  // 3) Flash attention
  attn_kernel<<<dim3(NHEADS, T_SEQ / 64), 128, ATTN_SMEM>>>(attn_p);
  // 4) Output projection
  split_hilo<<<(T_SEQ * HID / 4 + 255) / 256, 256>>>(
      (const float4*)attn_p, (float4*)ah, (float4*)al, T_SEQ * HID / 4);
  gemm_ldsm<<<dim3(HID / 128, T_SEQ / 128), 256, GEMM_SMEM>>>(
      ah, al, woh, out, HID, HID);
}

// round 6
// speedup vs baseline: 1.9170x; 1.2488x over previous
#include <cuda_runtime.h>
#include <cuda_bf16.h>
#include <cstdint>

#define T_SEQ 2048
#define HID   4096
#define QKV_N 6144
#define HD    128
#define NHEADS 32
#define ATTN_SCALE 0.08838834764831845f   // 128^-0.5
#define ATTN_SMEM (5 * 64 * 132 * 4)

// GEMM tiling: BM=BN=128, BK=32 (bf16), 3-stage cp.async pipeline, 2 CTAs/SM.
// Tile: 128 rows x 64B (32 bf16), seg-swizzled. 4 tiles/stage (Ah,Al,Bh,Bl).
#define TILE_B 8192
#define STG_BYTES (4 * TILE_B)
#define GEMM_SMEM (3 * STG_BYTES)

// Single dynamic-smem symbol for the whole TU (nvcc requirement)
extern __shared__ char dyn_smem[];

// ---------------------------------------------------------------------------
// Scratch (allocation-free rule: __device__ globals)
// ---------------------------------------------------------------------------
__device__ float g_qkv[(size_t)T_SEQ * QKV_N];   // QKV projection output
__device__ float g_attn[(size_t)T_SEQ * HID];    // attention output (pre-Wo)
__device__ __align__(16) __nv_bfloat16 g_ah[(size_t)T_SEQ * HID];   // A hi
__device__ __align__(16) __nv_bfloat16 g_al[(size_t)T_SEQ * HID];   // A lo
__device__ __align__(16) __nv_bfloat16 g_wqh[(size_t)QKV_N * HID];  // Wqkv^T hi [N,K]
__device__ __align__(16) __nv_bfloat16 g_wql[(size_t)QKV_N * HID];  // Wqkv^T lo
__device__ __align__(16) __nv_bfloat16 g_woh[(size_t)HID * HID];    // Wo^T hi
__device__ __align__(16) __nv_bfloat16 g_wol[(size_t)HID * HID];    // Wo^T lo

// ---------------------------------------------------------------------------
// helpers
// ---------------------------------------------------------------------------
__device__ __forceinline__ unsigned f2tf(float f) {
  unsigned u;
  asm("cvt.rna.tf32.f32 %0, %1;" : "=r"(u) : "f"(f));
  return u;
}

__device__ __forceinline__ uint32_t smem_u32(const void* p) {
  uint32_t a;
  asm("{ .reg .u64 t; cvta.to.shared.u64 t, %1; cvt.u32.u64 %0, t; }"
      : "=r"(a) : "l"(p));
  return a;
}

__device__ __forceinline__ void cp16(uint32_t dst, const void* src) {
  asm volatile("cp.async.cg.shared.global [%0], [%1], 16;"
               :: "r"(dst), "l"(src) : "memory");
}

__device__ __forceinline__ void ldsm4(unsigned r[4], uint32_t addr) {
  asm volatile("ldmatrix.sync.aligned.m8n8.x4.shared.b16 {%0,%1,%2,%3}, [%4];"
               : "=r"(r[0]), "=r"(r[1]), "=r"(r[2]), "=r"(r[3]) : "r"(addr));
}

// tf32 mma (attention kernel)
__device__ __forceinline__ void mma_tf32(float d[4], const unsigned a[4],
                                         unsigned b0, unsigned b1) {
  asm volatile(
      "mma.sync.aligned.m16n8k8.row.col.f32.tf32.tf32.f32 "
      "{%0,%1,%2,%3}, {%4,%5,%6,%7}, {%8,%9}, {%0,%1,%2,%3};"
      : "+f"(d[0]), "+f"(d[1]), "+f"(d[2]), "+f"(d[3])
      : "r"(a[0]), "r"(a[1]), "r"(a[2]), "r"(a[3]), "r"(b0), "r"(b1));
}

// bf16 mma m16n8k16 (GEMM)
__device__ __forceinline__ void mma_bf16(float d[4], const unsigned a[4],
                                         unsigned b0, unsigned b1) {
  asm volatile(
      "mma.sync.aligned.m16n8k16.row.col.f32.bf16.bf16.f32 "
      "{%0,%1,%2,%3}, {%4,%5,%6,%7}, {%8,%9}, {%0,%1,%2,%3};"
      : "+f"(d[0]), "+f"(d[1]), "+f"(d[2]), "+f"(d[3])
      : "r"(a[0]), "r"(a[1]), "r"(a[2]), "r"(a[3]), "r"(b0), "r"(b1));
}

__device__ __forceinline__ unsigned pack_bf2(float x, float y) {
  __nv_bfloat162 p = __floats2bfloat162_rn(x, y);
  return *reinterpret_cast<unsigned*>(&p);
}

// ---------------------------------------------------------------------------
// Prep kernels: bf16 hi/lo splits
// ---------------------------------------------------------------------------
__global__ void split_hilo_bf(const float4* __restrict__ X, uint2* __restrict__ Xh,
                              uint2* __restrict__ Xl, int n4) {
  int i = blockIdx.x * 256 + threadIdx.x;
  if (i >= n4) return;
  float4 v = X[i];
  float hx = __bfloat162float(__float2bfloat16(v.x));
  float hy = __bfloat162float(__float2bfloat16(v.y));
  float hz = __bfloat162float(__float2bfloat16(v.z));
  float hw = __bfloat162float(__float2bfloat16(v.w));
  uint2 h, l;
  h.x = pack_bf2(hx, hy);
  h.y = pack_bf2(hz, hw);
  l.x = pack_bf2(v.x - hx, v.y - hy);
  l.y = pack_bf2(v.z - hz, v.w - hw);
  Xh[i] = h;
  Xl[i] = l;
}

// W [K,N] row-major fp32 -> Wh/Wl [N,K] row-major bf16 hi/lo
__global__ void transpose_split_bf(const float* __restrict__ W,
                                   __nv_bfloat16* __restrict__ Wh,
                                   __nv_bfloat16* __restrict__ Wl, int K, int N) {
  __shared__ float t[32][33];
  const int n0 = blockIdx.x << 5, k0 = blockIdx.y << 5;
  const int tx = threadIdx.x, ty = threadIdx.y;  // 32 x 8
#pragma unroll
  for (int i = 0; i < 32; i += 8)
    t[ty + i][tx] = W[(size_t)(k0 + ty + i) * N + n0 + tx];
  __syncthreads();
#pragma unroll
  for (int i = 0; i < 32; i += 8) {
    float v = t[tx][ty + i];
    __nv_bfloat16 h = __float2bfloat16(v);
    size_t o = (size_t)(n0 + ty + i) * K + k0 + tx;
    Wh[o] = h;
    Wl[o] = __float2bfloat16(v - __bfloat162float(h));
  }
}

// ---------------------------------------------------------------------------
// 3-term bf16 GEMM (hh + lh + hl) == ~17-bit-mantissa exact A@B^T.
// A hi/lo [M,K] bf16, B hi/lo [N,K] bf16. BM=BN=128, BK=32, 3-stage cp.async,
// 2 CTAs/SM. 256 threads = 8 warps (4x2), warp tile 32x64.
// smem tile: 128 rows x 64B, swizzle: seg' = seg ^ ((row>>1)&3)  (conflict-free)
// ---------------------------------------------------------------------------
__global__ __launch_bounds__(256, 2) void gemm_bf3(
    const __nv_bfloat16* __restrict__ pAh, const __nv_bfloat16* __restrict__ pAl,
    const __nv_bfloat16* __restrict__ pBh, const __nv_bfloat16* __restrict__ pBl,
    float* __restrict__ C, int N, int K) {
  const uint32_t smb = smem_u32(dyn_smem);

  const int tid  = threadIdx.x;
  const int lane = tid & 31;
  const int warp = tid >> 5;
  const int wm = warp & 3;   // warp row 0..3 (32 M rows each)
  const int wn = warp >> 2;  // warp col 0..1 (64 N cols each)
  const int bm = blockIdx.y * 128;
  const int bn = blockIdx.x * 128;

  const __nv_bfloat16* aH = pAh + (size_t)bm * K;
  const __nv_bfloat16* aL = pAl + (size_t)bm * K;
  const __nv_bfloat16* bH = pBh + (size_t)bn * K;
  const __nv_bfloat16* bL = pBl + (size_t)bn * K;

  // cp.async mapping: thread -> row (tid>>1), two 16B segs ((tid&1)*2, +1)
  const int crow = tid >> 1;
  const int cs0  = (tid & 1) << 1;
  const int csw  = (crow >> 1) & 3;
  const uint32_t cd0 = (uint32_t)(crow * 64 + ((cs0 ^ csw) << 4));
  const uint32_t cd1 = (uint32_t)(crow * 64 + (((cs0 + 1) ^ csw) << 4));
  const int cse = cs0 << 3;  // element offset of first seg (8 bf16/seg)

  // ldmatrix lane geometry
  const int rowA = wm * 32 + (lane & 7) + ((lane >> 3) & 1) * 8;
  const int hcA  = (lane >> 4) & 1;
  const int swA  = (rowA >> 1) & 3;
  const uint32_t aofs = (uint32_t)(rowA * 64);
  const uint32_t xsa0 = (uint32_t)(((0 * 2 + hcA) ^ swA) << 4);
  const uint32_t xsa1 = (uint32_t)(((1 * 2 + hcA) ^ swA) << 4);

  const int rowB = wn * 64 + (lane & 7) + ((lane >> 4) & 1) * 8;
  const int hcB  = (lane >> 3) & 1;
  const int swB  = (rowB >> 1) & 3;
  const uint32_t bofs = (uint32_t)(rowB * 64);
  const uint32_t xsb0 = (uint32_t)(((0 * 2 + hcB) ^ swB) << 4);
  const uint32_t xsb1 = (uint32_t)(((1 * 2 + hcB) ^ swB) << 4);

  float acc[2][8][4];
#pragma unroll
  for (int i = 0; i < 2; i++)
#pragma unroll
    for (int j = 0; j < 8; j++)
#pragma unroll
      for (int r = 0; r < 4; r++) acc[i][j][r] = 0.f;

  const int NC = K >> 5;  // BK=32 chunks

#define ISSUE(c)                                                            \
  do {                                                                      \
    uint32_t sb = smb + (uint32_t)((c) % 3) * STG_BYTES;                    \
    size_t gg = (size_t)crow * K + ((c) << 5) + cse;                        \
    cp16(sb + cd0,              aH + gg); cp16(sb + cd1,              aH + gg + 8); \
    cp16(sb + TILE_B + cd0,     aL + gg); cp16(sb + TILE_B + cd1,     aL + gg + 8); \
    cp16(sb + 2 * TILE_B + cd0, bH + gg); cp16(sb + 2 * TILE_B + cd1, bH + gg + 8); \
    cp16(sb + 3 * TILE_B + cd0, bL + gg); cp16(sb + 3 * TILE_B + cd1, bL + gg + 8); \
    asm volatile("cp.async.commit_group;" ::: "memory");                    \
  } while (0)

  ISSUE(0);
  ISSUE(1);

  for (int c = 0; c < NC; ++c) {
    asm volatile("cp.async.wait_group 1;" ::: "memory");
    __syncthreads();
    if (c + 2 < NC) ISSUE(c + 2);

    const uint32_t sb  = smb + (uint32_t)(c % 3) * STG_BYTES;
    const uint32_t abh = sb + aofs;
    const uint32_t abl = abh + TILE_B;
    const uint32_t bbh = sb + 2 * TILE_B + bofs;
    const uint32_t bbl = bbh + TILE_B;

#pragma unroll
    for (int st = 0; st < 2; ++st) {  // two k16 steps in BK=32
      const uint32_t xa = st ? xsa1 : xsa0;
      const uint32_t xb = st ? xsb1 : xsb0;
      unsigned ah[2][4], al[2][4];
      ldsm4(ah[0], abh + xa);
      ldsm4(ah[1], abh + 1024 + xa);   // +16 rows
      ldsm4(al[0], abl + xa);
      ldsm4(al[1], abl + 1024 + xa);
#pragma unroll
      for (int p = 0; p < 4; ++p) {    // 4 n16 groups
        unsigned bh[4], bl[4];
        ldsm4(bh, bbh + p * 1024 + xb);
        ldsm4(bl, bbl + p * 1024 + xb);
#pragma unroll
        for (int mi = 0; mi < 2; ++mi)
#pragma unroll
          for (int sub = 0; sub < 2; ++sub) {
            const int ni = p * 2 + sub;
            mma_bf16(acc[mi][ni], ah[mi], bh[sub * 2], bh[sub * 2 + 1]);
            mma_bf16(acc[mi][ni], al[mi], bh[sub * 2], bh[sub * 2 + 1]);
            mma_bf16(acc[mi][ni], ah[mi], bl[sub * 2], bl[sub * 2 + 1]);
          }
      }
    }
  }
#undef ISSUE

  const int g  = lane >> 2;
  const int tg = lane & 3;
#pragma unroll
  for (int mi = 0; mi < 2; mi++) {
    int r0 = bm + wm * 32 + mi * 16 + g;
#pragma unroll
    for (int ni = 0; ni < 8; ni++) {
      int c = bn + wn * 64 + ni * 8 + tg * 2;
      C[(size_t)r0 * N + c]           = acc[mi][ni][0];
      C[(size_t)r0 * N + c + 1]       = acc[mi][ni][1];
      C[(size_t)(r0 + 8) * N + c]     = acc[mi][ni][2];
      C[(size_t)(r0 + 8) * N + c + 1] = acc[mi][ni][3];
    }
  }
}

// ---------------------------------------------------------------------------
// NeoX RoPE, in-place on g_qkv's Q (heads 0..31) and K (heads 32..39).
// ---------------------------------------------------------------------------
__global__ void rope_kernel(const int* __restrict__ positions) {
  const int bid = blockIdx.x;
  const int t  = bid / 40;
  const int hh = bid % 40;
  const int d  = threadIdx.x;  // 0..63

  const float pos = (float)positions[t];
  const float inv = expf(-((float)d * (1.0f / 64.0f)) * 13.815510557964274f);
  const float fr = pos * inv;
  const float c = cosf(fr);
  const float s = sinf(fr);

  float* base = g_qkv + (size_t)t * QKV_N + (hh < 32 ? hh * HD : HID + (hh - 32) * HD);
  const float x1 = base[d];
  const float x2 = base[d + 64];
  base[d]      = x1 * c - x2 * s;
  base[d + 64] = x2 * c + x1 * s;
}

// ---------------------------------------------------------------------------
// Flash attention (proven: contributes ~2.8e-4 rel_err)
// ---------------------------------------------------------------------------
__global__ void attn_kernel(float* __restrict__ out) {
  unsigned* sm = reinterpret_cast<unsigned*>(dyn_smem);
  const int SQ = 64 * 132;
  unsigned* Qh = sm;
  unsigned* Ql = Qh + SQ;
  unsigned* Kh = Ql + SQ;
  unsigned* Kl = Kh + SQ;
  unsigned* Vs = Kl + SQ;
  unsigned* Ps = Kh;  // reused after S; stride 68

  const int h   = blockIdx.x;
  const int qt  = blockIdx.y;
  const int kvh = h >> 2;
  const int q0  = qt * 64;
  const int tid = threadIdx.x;
  const int lane = tid & 31;
  const int w  = tid >> 5;
  const int g  = lane >> 2;
  const int tg = lane & 3;

  for (int i = tid; i < 64 * 32; i += 128) {
    int r  = i >> 5;
    int c4 = (i & 31) * 4;
    float4 v = *reinterpret_cast<const float4*>(
        &g_qkv[(size_t)(q0 + r) * QKV_N + h * HD + c4]);
    float vv[4] = {v.x, v.y, v.z, v.w};
#pragma unroll
    for (int u = 0; u < 4; u++) {
      unsigned hi = f2tf(vv[u]);
      Qh[r * 132 + c4 + u] = hi;
      Ql[r * 132 + c4 + u] = f2tf(vv[u] - __uint_as_float(hi));
    }
  }

  float m0 = -1e30f, m1 = -1e30f, l0 = 0.f, l1 = 0.f;
  float O[16][4];
#pragma unroll
  for (int i = 0; i < 16; i++)
#pragma unroll
    for (int r = 0; r < 4; r++) O[i][r] = 0.f;

  for (int j = 0; j <= qt; ++j) {
    __syncthreads();
    for (int i = tid; i < 64 * 32; i += 128) {
      int r  = i >> 5;
      int c4 = (i & 31) * 4;
      const size_t base = (size_t)(j * 64 + r) * QKV_N + kvh * HD + c4;
      float4 kv = *reinterpret_cast<const float4*>(&g_qkv[base + 4096]);
      float4 vv = *reinterpret_cast<const float4*>(&g_qkv[base + 5120]);
      float ka[4] = {kv.x, kv.y, kv.z, kv.w};
      float va[4] = {vv.x, vv.y, vv.z, vv.w};
#pragma unroll
      for (int u = 0; u < 4; u++) {
        unsigned hi = f2tf(ka[u]);
        Kh[r * 132 + c4 + u] = hi;
        Kl[r * 132 + c4 + u] = f2tf(ka[u] - __uint_as_float(hi));
        Vs[r * 132 + c4 + u] = f2tf(va[u]);
      }
    }
    __syncthreads();

    float s[8][4];
#pragma unroll
    for (int ni = 0; ni < 8; ni++)
#pragma unroll
      for (int r = 0; r < 4; r++) s[ni][r] = 0.f;

    const int ra = (w * 16 + g) * 132;
    const int rb = (w * 16 + g + 8) * 132;
#pragma unroll
    for (int d0 = 0; d0 < 128; d0 += 8) {
      unsigned qh[4], ql[4];
      qh[0] = Qh[ra + d0 + tg];     ql[0] = Ql[ra + d0 + tg];
      qh[1] = Qh[rb + d0 + tg];     ql[1] = Ql[rb + d0 + tg];
      qh[2] = Qh[ra + d0 + tg + 4]; ql[2] = Ql[ra + d0 + tg + 4];
      qh[3] = Qh[rb + d0 + tg + 4]; ql[3] = Ql[rb + d0 + tg + 4];
#pragma unroll
      for (int ni = 0; ni < 8; ni++) {
        int rn = (ni * 8 + g) * 132;
        unsigned kh0 = Kh[rn + d0 + tg], kh1 = Kh[rn + d0 + tg + 4];
        unsigned kl0 = Kl[rn + d0 + tg], kl1 = Kl[rn + d0 + tg + 4];
        mma_tf32(s[ni], qh, kh0, kh1);
        mma_tf32(s[ni], ql, kh0, kh1);
        mma_tf32(s[ni], qh, kl0, kl1);
      }
    }
    __syncthreads();

    const int gr0 = q0 + w * 16 + g;
    const int gr1 = gr0 + 8;
    float tm0 = -1e30f, tm1 = -1e30f;
#pragma unroll
    for (int ni = 0; ni < 8; ni++) {
#pragma unroll
      for (int cc = 0; cc < 2; cc++) {
        int gc = j * 64 + ni * 8 + tg * 2 + cc;
        float v0 = s[ni][cc] * ATTN_SCALE;
        float v1 = s[ni][2 + cc] * ATTN_SCALE;
        if (gc > gr0) v0 = -1e30f;
        if (gc > gr1) v1 = -1e30f;
        s[ni][cc] = v0;
        s[ni][2 + cc] = v1;
        tm0 = fmaxf(tm0, v0);
        tm1 = fmaxf(tm1, v1);
      }
    }
    tm0 = fmaxf(tm0, __shfl_xor_sync(0xffffffffu, tm0, 1));
    tm0 = fmaxf(tm0, __shfl_xor_sync(0xffffffffu, tm0, 2));
    tm1 = fmaxf(tm1, __shfl_xor_sync(0xffffffffu, tm1, 1));
    tm1 = fmaxf(tm1, __shfl_xor_sync(0xffffffffu, tm1, 2));

    float nm0 = fmaxf(m0, tm0), nm1 = fmaxf(m1, tm1);
    float a0 = expf(m0 - nm0), a1 = expf(m1 - nm1);

    const int pa = (w * 16 + g) * 68;
    const int pb = (w * 16 + g + 8) * 68;
    float ps0 = 0.f, ps1 = 0.f;
#pragma unroll
    for (int ni = 0; ni < 8; ni++) {
      float p00 = expf(s[ni][0] - nm0);
      float p01 = expf(s[ni][1] - nm0);
      float p10 = expf(s[ni][2] - nm1);
      float p11 = expf(s[ni][3] - nm1);
      ps0 += p00 + p01;
      ps1 += p10 + p11;
      Ps[pa + ni * 8 + tg * 2]     = f2tf(p00);
      Ps[pa + ni * 8 + tg * 2 + 1] = f2tf(p01);
      Ps[pb + ni * 8 + tg * 2]     = f2tf(p10);
      Ps[pb + ni * 8 + tg * 2 + 1] = f2tf(p11);
    }
    ps0 += __shfl_xor_sync(0xffffffffu, ps0, 1);
    ps0 += __shfl_xor_sync(0xffffffffu, ps0, 2);
    ps1 += __shfl_xor_sync(0xffffffffu, ps1, 1);
    ps1 += __shfl_xor_sync(0xffffffffu, ps1, 2);

    l0 = l0 * a0 + ps0;
    l1 = l1 * a1 + ps1;
    m0 = nm0;
    m1 = nm1;
#pragma unroll
    for (int ni = 0; ni < 16; ni++) {
      O[ni][0] *= a0; O[ni][1] *= a0;
      O[ni][2] *= a1; O[ni][3] *= a1;
    }
    __syncwarp();

#pragma unroll
    for (int kk = 0; kk < 64; kk += 8) {
      unsigned pf[4];
      pf[0] = Ps[pa + kk + tg];
      pf[1] = Ps[pb + kk + tg];
      pf[2] = Ps[pa + kk + tg + 4];
      pf[3] = Ps[pb + kk + tg + 4];
#pragma unroll
      for (int ni = 0; ni < 16; ni++) {
        unsigned b0 = Vs[(kk + tg) * 132 + ni * 8 + g];
        unsigned b1 = Vs[(kk + tg + 4) * 132 + ni * 8 + g];
        mma_tf32(O[ni], pf, b0, b1);
      }
    }
  }

  const float inv0 = 1.f / l0;
  const float inv1 = 1.f / l1;
  const int gr0 = q0 + w * 16 + g;
#pragma unroll
  for (int ni = 0; ni < 16; ni++) {
    int c = h * HD + ni * 8 + tg * 2;
    out[(size_t)gr0 * HID + c]           = O[ni][0] * inv0;
    out[(size_t)gr0 * HID + c + 1]       = O[ni][1] * inv0;
    out[(size_t)(gr0 + 8) * HID + c]     = O[ni][2] * inv1;
    out[(size_t)(gr0 + 8) * HID + c + 1] = O[ni][3] * inv1;
  }
}

// ---------------------------------------------------------------------------
// launch
// ---------------------------------------------------------------------------
extern "C" void kernel_launch(void* const* d_in, const int* in_sizes, int n_in,
                              void* d_out, int out_size) {
  (void)in_sizes; (void)n_in; (void)out_size;
  const int*   positions = (const int*)d_in[0];
  const float* hidden    = (const float*)d_in[1];
  const float* Wqkv      = (const float*)d_in[2];
  const float* Wo        = (const float*)d_in[3];
  float* out = (float*)d_out;

  float *qkv_p, *attn_p;
  __nv_bfloat16 *ah, *al, *wqh, *wql, *woh, *wol;
  cudaGetSymbolAddress((void**)&qkv_p, g_qkv);
  cudaGetSymbolAddress((void**)&attn_p, g_attn);
  cudaGetSymbolAddress((void**)&ah, g_ah);
  cudaGetSymbolAddress((void**)&al, g_al);
  cudaGetSymbolAddress((void**)&wqh, g_wqh);
  cudaGetSymbolAddress((void**)&wql, g_wql);
  cudaGetSymbolAddress((void**)&woh, g_woh);
  cudaGetSymbolAddress((void**)&wol, g_wol);

  cudaFuncSetAttribute(attn_kernel, cudaFuncAttributeMaxDynamicSharedMemorySize,
                       ATTN_SMEM);
  cudaFuncSetAttribute(gemm_bf3, cudaFuncAttributeMaxDynamicSharedMemorySize,
                       GEMM_SMEM);

  // Prep: transpose+split weights to bf16 hi/lo, split activations
  transpose_split_bf<<<dim3(QKV_N / 32, HID / 32), dim3(32, 8)>>>(Wqkv, wqh, wql,
                                                                  HID, QKV_N);
  transpose_split_bf<<<dim3(HID / 32, HID / 32), dim3(32, 8)>>>(Wo, woh, wol,
                                                                HID, HID);
  split_hilo_bf<<<(T_SEQ * HID / 4 + 255) / 256, 256>>>(
      (const float4*)hidden, (uint2*)ah, (uint2*)al, T_SEQ * HID / 4);

  // 1) QKV projection
  gemm_bf3<<<dim3(QKV_N / 128, T_SEQ / 128), 256, GEMM_SMEM>>>(
      ah, al, wqh, wql, qkv_p, QKV_N, HID);
  // 2) RoPE
  rope_kernel<<<T_SEQ * 40, 64>>>(positions);
  // 3) Flash attention
  attn_kernel<<<dim3(NHEADS, T_SEQ / 64), 128, ATTN_SMEM>>>(attn_p);
  // 4) Output projection
  split_hilo_bf<<<(T_SEQ * HID / 4 + 255) / 256, 256>>>(
      (const float4*)attn_p, (uint2*)ah, (uint2*)al, T_SEQ * HID / 4);
  gemm_bf3<<<dim3(HID / 128, T_SEQ / 128), 256, GEMM_SMEM>>>(
      ah, al, woh, wol, out, HID, HID);
}